// round 2
// baseline (speedup 1.0000x reference)
#include <cuda_runtime.h>

#define ND 600
#define NPRO 19081
#define NSE 964
#define EMB 128
#define FEAT 2048
#define NE 1200000
#define NPAIRS 8192
#define NANCH 8192
#define NV 19681
#define KSPLIT 16
#define MPAD 640

// ---------------- scratch (static device globals; no allocation) ----------------
__device__ float g_part[KSPLIT * MPAD * EMB];   // mlp1 split-K partials (5.2 MB)
__device__ float g_h1[ND * EMB];                // relu(drugF @ W1^T + b1)
__device__ float g_xd[ND * EMB];                // relu(h1 @ W2^T + b2)  == xF[:600]
__device__ float g_agg[ND * EMB];               // mean-aggregated neighbors (600 rows)
__device__ float g_x600[ND * EMB];              // sage layer-1 output, rows < 600
__device__ float g_U[ND * EMB];                 // x600 @ Wa^T
__device__ float g_V[ND * EMB];                 // x600 @ Wb^T
__device__ float g_out1[NPAIRS * EMB];          // relu(U[a]+V[b]+outb1)
__device__ int   g_deg[ND];
__device__ int   g_cursor[ND];
__device__ int   g_rowptr[ND + 1];
__device__ float g_invdeg[ND];
__device__ int   g_csr[NE];                     // only ~36K used; capacity safe
__device__ float g_W2t[EMB * EMB];              // W2 transposed   [k][o]
__device__ float g_Wlt[EMB * EMB];              // sageWl[1]^T     [k][o]
__device__ float g_Wrt[EMB * EMB];              // sageWr[1]^T     [k][o]
__device__ float g_W1pt[2 * EMB * EMB];         // outW1^T         [k(0..255)][o]

// ---------------- tiny init ----------------
__global__ void k_zero() {
    int i = blockIdx.x * blockDim.x + threadIdx.x;
    if (i < ND) { g_deg[i] = 0; g_cursor[i] = 0; }
}

// transpose the small weight matrices once per launch
__global__ void k_prep(const float* __restrict__ W2, const float* __restrict__ Wl,
                       const float* __restrict__ Wr, const float* __restrict__ oW1) {
    int idx = blockIdx.x * 1024 + threadIdx.x;          // 81920 total
    if (idx < 16384) {
        int k = idx >> 7, o = idx & 127;
        g_W2t[idx] = W2[o * 128 + k];
    } else if (idx < 32768) {
        int f = idx - 16384; int k = f >> 7, o = f & 127;
        g_Wlt[f] = Wl[o * 128 + k];
    } else if (idx < 49152) {
        int f = idx - 32768; int k = f >> 7, o = f & 127;
        g_Wrt[f] = Wr[o * 128 + k];
    } else {
        int f = idx - 49152; int k = f >> 7, o = f & 127;   // k in [0,256)
        g_W1pt[f] = oW1[o * 256 + k];
    }
}

// ---------------- edge passes (only dst < 600 matters) ----------------
__global__ void k_hist(const int* __restrict__ ei) {
    int stride = gridDim.x * blockDim.x;
    for (int i = blockIdx.x * blockDim.x + threadIdx.x; i < NE; i += stride) {
        int d = ei[NE + i];
        if (d < ND) atomicAdd(&g_deg[d], 1);
    }
}

__global__ void k_scan() {   // 1 block, 1024 threads: inclusive scan of 600 counts
    __shared__ int s[1024];
    int t = threadIdx.x;
    int d = (t < ND) ? g_deg[t] : 0;
    s[t] = d;
    __syncthreads();
    for (int off = 1; off < 1024; off <<= 1) {
        int v = (t >= off) ? s[t - off] : 0;
        __syncthreads();
        s[t] += v;
        __syncthreads();
    }
    if (t < ND) {
        g_rowptr[t + 1] = s[t];
        g_invdeg[t] = 1.f / fmaxf((float)d, 1.f);
    }
    if (t == 0) g_rowptr[0] = 0;
}

__global__ void k_fill(const int* __restrict__ ei) {
    int stride = gridDim.x * blockDim.x;
    for (int i = blockIdx.x * blockDim.x + threadIdx.x; i < NE; i += stride) {
        int d = ei[NE + i];
        if (d < ND) {
            int p = atomicAdd(&g_cursor[d], 1);
            g_csr[g_rowptr[d] + p] = ei[i];
        }
    }
}

// ---------------- MLP1: split-K tiled SGEMM, M=600 K=2048 N=128 ----------------
// grid (10, 16): 64-row tile x full-N, 128-wide K slice per block. 256 threads (32x8).
__global__ void k_mlp1(const float* __restrict__ A, const float* __restrict__ W) {
    __shared__ __align__(16) float As[16][64];
    __shared__ __align__(16) float Bs[16][128];
    int tx = threadIdx.x, ty = threadIdx.y;
    int tid = ty * 32 + tx;
    int rowBase = blockIdx.x * 64;
    int kbase = blockIdx.y * 128;
    float acc[8][4];
#pragma unroll
    for (int i = 0; i < 8; i++)
#pragma unroll
        for (int j = 0; j < 4; j++) acc[i][j] = 0.f;

    for (int kk = 0; kk < 8; kk++) {
        int r = tid >> 2, c4 = tid & 3;
        int row = rowBase + r;
        float4 va = make_float4(0.f, 0.f, 0.f, 0.f);
        if (row < ND) va = *(const float4*)(A + row * FEAT + kbase + kk * 16 + c4 * 4);
        As[c4 * 4 + 0][r] = va.x; As[c4 * 4 + 1][r] = va.y;
        As[c4 * 4 + 2][r] = va.z; As[c4 * 4 + 3][r] = va.w;
#pragma unroll
        for (int q = 0; q < 2; q++) {
            int idx = tid + q * 256;
            int wr = idx >> 2, wc = idx & 3;
            float4 vb = *(const float4*)(W + wr * FEAT + kbase + kk * 16 + wc * 4);
            Bs[wc * 4 + 0][wr] = vb.x; Bs[wc * 4 + 1][wr] = vb.y;
            Bs[wc * 4 + 2][wr] = vb.z; Bs[wc * 4 + 3][wr] = vb.w;
        }
        __syncthreads();
#pragma unroll
        for (int k = 0; k < 16; k++) {
            float a[8], b[4];
            *(float4*)(a)     = *(const float4*)&As[k][ty * 8];
            *(float4*)(a + 4) = *(const float4*)&As[k][ty * 8 + 4];
            *(float4*)(b)     = *(const float4*)&Bs[k][tx * 4];
#pragma unroll
            for (int i = 0; i < 8; i++)
#pragma unroll
                for (int j = 0; j < 4; j++) acc[i][j] += a[i] * b[j];
        }
        __syncthreads();
    }
    float* out = g_part + blockIdx.y * (MPAD * EMB) + rowBase * EMB;
#pragma unroll
    for (int i = 0; i < 8; i++) {
        float4 v = make_float4(acc[i][0], acc[i][1], acc[i][2], acc[i][3]);
        *(float4*)(out + (ty * 8 + i) * EMB + tx * 4) = v;
    }
}

__global__ void k_mlp1_reduce(const float* __restrict__ b1) {
    int idx = blockIdx.x * 1024 + threadIdx.x;   // 75*1024 == 76800 exactly
    float s = 0.f;
#pragma unroll
    for (int ks = 0; ks < KSPLIT; ks++) s += g_part[ks * MPAD * EMB + idx];
    s += b1[idx & 127];
    g_h1[idx] = fmaxf(s, 0.f);
}

// ---------------- warp-per-row skinny GEMMs (K=128, N=128, L1-resident W^T) ------
__global__ void k_mlp2(const float* __restrict__ b2) {
    int warp = (blockIdx.x * blockDim.x + threadIdx.x) >> 5;
    int lane = threadIdx.x & 31;
    if (warp >= ND) return;
    const float* arow = g_h1 + warp * EMB;
    float4 acc = *(const float4*)(b2 + lane * 4);
#pragma unroll
    for (int k0 = 0; k0 < EMB; k0 += 32) {
        float av = arow[k0 + lane];
#pragma unroll
        for (int j = 0; j < 32; j++) {
            float a = __shfl_sync(0xffffffffu, av, j);
            float4 w = *(const float4*)&g_W2t[(k0 + j) * EMB + lane * 4];
            acc.x += a * w.x; acc.y += a * w.y; acc.z += a * w.z; acc.w += a * w.w;
        }
    }
    acc.x = fmaxf(acc.x, 0.f); acc.y = fmaxf(acc.y, 0.f);
    acc.z = fmaxf(acc.z, 0.f); acc.w = fmaxf(acc.w, 0.f);
    *(float4*)(g_xd + warp * EMB + lane * 4) = acc;
}

// ---------------- neighbor aggregation: 600 CSR rows, block-per-node -------------
__global__ void k_agg(const float* __restrict__ protEmb) {
    int v = blockIdx.x;
    int t = threadIdx.x;                  // 128 threads = 128 cols
    __shared__ int sidx[128];
    int beg = g_rowptr[v], end = g_rowptr[v + 1];
    float sum = 0.f;
    for (int base = beg; base < end; base += 128) {
        int n = min(128, end - base);
        __syncthreads();
        if (t < n) sidx[t] = g_csr[base + t];
        __syncthreads();
        int j = 0;
        for (; j + 4 <= n; j += 4) {
            int s0 = sidx[j], s1 = sidx[j + 1], s2 = sidx[j + 2], s3 = sidx[j + 3];
            const float* p0 = (s0 < ND) ? g_xd + s0 * EMB : protEmb + (s0 - ND) * EMB;
            const float* p1 = (s1 < ND) ? g_xd + s1 * EMB : protEmb + (s1 - ND) * EMB;
            const float* p2 = (s2 < ND) ? g_xd + s2 * EMB : protEmb + (s2 - ND) * EMB;
            const float* p3 = (s3 < ND) ? g_xd + s3 * EMB : protEmb + (s3 - ND) * EMB;
            float v0 = p0[t], v1 = p1[t], v2 = p2[t], v3 = p3[t];
            sum += (v0 + v1) + (v2 + v3);
        }
        for (; j < n; j++) {
            int s0 = sidx[j];
            const float* p0 = (s0 < ND) ? g_xd + s0 * EMB : protEmb + (s0 - ND) * EMB;
            sum += p0[t];
        }
    }
    g_agg[v * EMB + t] = sum * g_invdeg[v];
}

// ---------------- SAGE layer 1 (only layer that matters): K=256 concat ----------
__global__ void k_sage(const float* __restrict__ bl) {
    int warp = (blockIdx.x * blockDim.x + threadIdx.x) >> 5;
    int lane = threadIdx.x & 31;
    if (warp >= ND) return;
    const float* a1 = g_agg + warp * EMB;
    const float* a2 = g_xd + warp * EMB;
    float4 acc = *(const float4*)(bl + lane * 4);
#pragma unroll
    for (int k0 = 0; k0 < EMB; k0 += 32) {
        float av1 = a1[k0 + lane];
        float av2 = a2[k0 + lane];
#pragma unroll
        for (int j = 0; j < 32; j++) {
            float x1 = __shfl_sync(0xffffffffu, av1, j);
            float x2 = __shfl_sync(0xffffffffu, av2, j);
            float4 wl = *(const float4*)&g_Wlt[(k0 + j) * EMB + lane * 4];
            float4 wr = *(const float4*)&g_Wrt[(k0 + j) * EMB + lane * 4];
            acc.x += x1 * wl.x + x2 * wr.x;
            acc.y += x1 * wl.y + x2 * wr.y;
            acc.z += x1 * wl.z + x2 * wr.z;
            acc.w += x1 * wl.w + x2 * wr.w;
        }
    }
    acc.x = fmaxf(acc.x, 0.f); acc.y = fmaxf(acc.y, 0.f);
    acc.z = fmaxf(acc.z, 0.f); acc.w = fmaxf(acc.w, 0.f);
    *(float4*)(g_x600 + warp * EMB + lane * 4) = acc;
}

// ---------------- U = x600 @ Wa^T, V = x600 @ Wb^T -------------------------------
__global__ void k_uv() {
    int warp = (blockIdx.x * blockDim.x + threadIdx.x) >> 5;
    int lane = threadIdx.x & 31;
    if (warp >= ND) return;
    const float* arow = g_x600 + warp * EMB;
    float4 u = make_float4(0.f, 0.f, 0.f, 0.f);
    float4 v = make_float4(0.f, 0.f, 0.f, 0.f);
#pragma unroll
    for (int k0 = 0; k0 < EMB; k0 += 32) {
        float av = arow[k0 + lane];
#pragma unroll
        for (int j = 0; j < 32; j++) {
            float a = __shfl_sync(0xffffffffu, av, j);
            float4 wu = *(const float4*)&g_W1pt[(k0 + j) * EMB + lane * 4];
            float4 wv = *(const float4*)&g_W1pt[(128 + k0 + j) * EMB + lane * 4];
            u.x += a * wu.x; u.y += a * wu.y; u.z += a * wu.z; u.w += a * wu.w;
            v.x += a * wv.x; v.y += a * wv.y; v.z += a * wv.z; v.w += a * wv.w;
        }
    }
    *(float4*)(g_U + warp * EMB + lane * 4) = u;
    *(float4*)(g_V + warp * EMB + lane * 4) = v;
}

// ---------------- out1 = relu(U[a] + V[b] + outb1)  (the collapsed pair GEMM) ----
__global__ void k_pairadd(const int* __restrict__ tpl, const float* __restrict__ outb1) {
    int idx = blockIdx.x * 256 + threadIdx.x;     // 8192 * 32 float4s
    int p = idx >> 5, c = idx & 31;
    int ia = tpl[2 * p], ib = tpl[2 * p + 1];
    float4 u = ((const float4*)g_U)[ia * 32 + c];
    float4 v = ((const float4*)g_V)[ib * 32 + c];
    float4 b = ((const float4*)outb1)[c];
    float4 r;
    r.x = fmaxf(u.x + v.x + b.x, 0.f);
    r.y = fmaxf(u.y + v.y + b.y, 0.f);
    r.z = fmaxf(u.z + v.z + b.z, 0.f);
    r.w = fmaxf(u.w + v.w + b.w, 0.f);
    ((float4*)g_out1)[p * 32 + c] = r;
}

// ---------------- final: per-anchor single dot (never materialize 8192x964) ------
__global__ void k_final(const int* __restrict__ anch, const float* __restrict__ oW2,
                        const float* __restrict__ ob2, float* __restrict__ out) {
    int w = (blockIdx.x * blockDim.x + threadIdx.x) >> 5;
    int lane = threadIdx.x & 31;
    if (w >= NANCH) return;
    int a = anch[w];
    int p = a / NSE;
    int s = a - p * NSE;
    float4 x = ((const float4*)(g_out1 + p * EMB))[lane];
    float4 y = ((const float4*)(oW2 + s * EMB))[lane];
    float d = x.x * y.x + x.y * y.y + x.z * y.z + x.w * y.w;
#pragma unroll
    for (int off = 16; off; off >>= 1) d += __shfl_xor_sync(0xffffffffu, d, off);
    if (lane == 0) out[w] = fmaxf(d + ob2[s], 0.f);
}

// ---------------- launch ----------------
extern "C" void kernel_launch(void* const* d_in, const int* in_sizes, int n_in,
                              void* d_out, int out_size) {
    const int*   ei      = (const int*)d_in[0];
    const float* drugF   = (const float*)d_in[1];
    const int*   tpl     = (const int*)d_in[2];
    const int*   anch    = (const int*)d_in[3];
    const float* W1      = (const float*)d_in[4];
    const float* b1      = (const float*)d_in[5];
    const float* W2      = (const float*)d_in[6];
    const float* b2      = (const float*)d_in[7];
    const float* protEmb = (const float*)d_in[8];
    const float* sageWl  = (const float*)d_in[9];
    const float* sagebl  = (const float*)d_in[10];
    const float* sageWr  = (const float*)d_in[11];
    const float* outW1   = (const float*)d_in[12];
    const float* outb1   = (const float*)d_in[13];
    const float* outW2   = (const float*)d_in[14];
    const float* outb2   = (const float*)d_in[15];
    float* out = (float*)d_out;

    k_zero<<<3, 256>>>();
    k_prep<<<80, 1024>>>(W2, sageWl + EMB * EMB, sageWr + EMB * EMB, outW1);
    k_hist<<<1184, 256>>>(ei);
    k_mlp1<<<dim3(10, 16), dim3(32, 8)>>>(drugF, W1);
    k_scan<<<1, 1024>>>();
    k_fill<<<1184, 256>>>(ei);
    k_mlp1_reduce<<<75, 1024>>>(b1);
    k_mlp2<<<75, 256>>>(b2);
    k_agg<<<600, 128>>>(protEmb);
    k_sage<<<75, 256>>>(sagebl + EMB);
    k_uv<<<75, 256>>>();
    k_pairadd<<<1024, 256>>>(tpl, outb1);
    k_final<<<1024, 256>>>(anch, outW2, outb2, out);
}

// round 3
// speedup vs baseline: 1.0968x; 1.0968x over previous
#include <cuda_runtime.h>

#define ND 600
#define NPRO 19081
#define NSE 964
#define EMB 128
#define FEAT 2048
#define NE 1200000
#define NPAIRS 8192
#define NANCH 8192
#define NV 19681
#define KSPLIT 32
#define MPAD 640
#define BCAP 160

// ---------------- scratch (static device globals; no allocation) ----------------
__device__ float g_part[KSPLIT * MPAD * EMB];   // mlp1 split-K partials (10.5 MB)
__device__ float g_xd[ND * EMB];                // relu MLP output == xF[:600]
__device__ float g_agg[ND * EMB];               // mean-aggregated neighbors
__device__ float g_U[ND * EMB];                 // x600 @ Wa^T
__device__ float g_V[ND * EMB];                 // x600 @ Wb^T
__device__ int   g_deg[ND];                     // degree == bucket cursor
__device__ int   g_bkt[ND * BCAP];              // per-node src buckets
__device__ float g_W2t[EMB * EMB];              // W2^T        [k][o]
__device__ float g_Wlt[EMB * EMB];              // sageWl[1]^T [k][o]
__device__ float g_Wrt[EMB * EMB];              // sageWr[1]^T [k][o]
__device__ float g_W1pt[2 * EMB * EMB];         // outW1^T     [k(0..255)][o]

// ---------------- init: zero deg + transpose small weights ----------------
__global__ void k_init(const float* __restrict__ W2, const float* __restrict__ Wl,
                       const float* __restrict__ Wr, const float* __restrict__ oW1) {
    int idx = blockIdx.x * 1024 + threadIdx.x;          // 81 blocks: 82944 threads
    if (idx < 16384) {
        int k = idx >> 7, o = idx & 127;
        g_W2t[idx] = W2[o * 128 + k];
    } else if (idx < 32768) {
        int f = idx - 16384; int k = f >> 7, o = f & 127;
        g_Wlt[f] = Wl[o * 128 + k];
    } else if (idx < 49152) {
        int f = idx - 32768; int k = f >> 7, o = f & 127;
        g_Wrt[f] = Wr[o * 128 + k];
    } else if (idx < 81920) {
        int f = idx - 49152; int k = f >> 7, o = f & 127;   // k in [0,256)
        g_W1pt[f] = oW1[o * 256 + k];
    } else if (idx - 81920 < ND) {
        g_deg[idx - 81920] = 0;
    }
}

// ---------------- single edge pass: deg-count + bucket scatter --------------------
__global__ void k_edges(const int* __restrict__ ei) {
    int stride = gridDim.x * blockDim.x;
    for (int i = blockIdx.x * blockDim.x + threadIdx.x; i < NE; i += stride) {
        int d = ei[NE + i];
        if (d < ND) {
            int p = atomicAdd(&g_deg[d], 1);
            g_bkt[d * BCAP + p] = ei[i];
        }
    }
}

// ---------------- MLP1: split-K tiled SGEMM, M=600 K=2048 N=128 ----------------
// grid (10, 32): 64-row tile x full-N, 64-wide K slice per block. 256 threads (32x8).
__global__ void k_mlp1(const float* __restrict__ A, const float* __restrict__ W) {
    __shared__ __align__(16) float As[16][64];
    __shared__ __align__(16) float Bs[16][128];
    int tx = threadIdx.x, ty = threadIdx.y;
    int tid = ty * 32 + tx;
    int rowBase = blockIdx.x * 64;
    int kbase = blockIdx.y * 64;
    float acc[8][4];
#pragma unroll
    for (int i = 0; i < 8; i++)
#pragma unroll
        for (int j = 0; j < 4; j++) acc[i][j] = 0.f;

    for (int kk = 0; kk < 4; kk++) {
        int r = tid >> 2, c4 = tid & 3;
        int row = rowBase + r;
        float4 va = make_float4(0.f, 0.f, 0.f, 0.f);
        if (row < ND) va = *(const float4*)(A + row * FEAT + kbase + kk * 16 + c4 * 4);
        As[c4 * 4 + 0][r] = va.x; As[c4 * 4 + 1][r] = va.y;
        As[c4 * 4 + 2][r] = va.z; As[c4 * 4 + 3][r] = va.w;
#pragma unroll
        for (int q = 0; q < 2; q++) {
            int idx = tid + q * 256;
            int wr = idx >> 2, wc = idx & 3;
            float4 vb = *(const float4*)(W + wr * FEAT + kbase + kk * 16 + wc * 4);
            Bs[wc * 4 + 0][wr] = vb.x; Bs[wc * 4 + 1][wr] = vb.y;
            Bs[wc * 4 + 2][wr] = vb.z; Bs[wc * 4 + 3][wr] = vb.w;
        }
        __syncthreads();
#pragma unroll
        for (int k = 0; k < 16; k++) {
            float a[8], b[4];
            *(float4*)(a)     = *(const float4*)&As[k][ty * 8];
            *(float4*)(a + 4) = *(const float4*)&As[k][ty * 8 + 4];
            *(float4*)(b)     = *(const float4*)&Bs[k][tx * 4];
#pragma unroll
            for (int i = 0; i < 8; i++)
#pragma unroll
                for (int j = 0; j < 4; j++) acc[i][j] += a[i] * b[j];
        }
        __syncthreads();
    }
    float* out = g_part + blockIdx.y * (MPAD * EMB) + rowBase * EMB;
#pragma unroll
    for (int i = 0; i < 8; i++) {
        float4 v = make_float4(acc[i][0], acc[i][1], acc[i][2], acc[i][3]);
        *(float4*)(out + (ty * 8 + i) * EMB + tx * 4) = v;
    }
}

// ---------------- fused: split-K reduce + bias + relu + MLP2 ----------------------
__global__ void k_mlp12(const float* __restrict__ b1, const float* __restrict__ b2) {
    int warp = (blockIdx.x * blockDim.x + threadIdx.x) >> 5;
    int lane = threadIdx.x & 31;
    if (warp >= ND) return;
    float h[4];
#pragma unroll
    for (int q = 0; q < 4; q++) {
        int col = q * 32 + lane;
        float s = b1[col];
        const float* p = g_part + warp * EMB + col;
#pragma unroll
        for (int ks = 0; ks < KSPLIT; ks++) s += p[ks * (MPAD * EMB)];
        h[q] = fmaxf(s, 0.f);
    }
    float4 acc = *(const float4*)(b2 + lane * 4);
#pragma unroll
    for (int q = 0; q < 4; q++) {
        float av = h[q];
#pragma unroll
        for (int j = 0; j < 32; j++) {
            float a = __shfl_sync(0xffffffffu, av, j);
            float4 w = *(const float4*)&g_W2t[(q * 32 + j) * EMB + lane * 4];
            acc.x += a * w.x; acc.y += a * w.y; acc.z += a * w.z; acc.w += a * w.w;
        }
    }
    acc.x = fmaxf(acc.x, 0.f); acc.y = fmaxf(acc.y, 0.f);
    acc.z = fmaxf(acc.z, 0.f); acc.w = fmaxf(acc.w, 0.f);
    *(float4*)(g_xd + warp * EMB + lane * 4) = acc;
}

// ---------------- neighbor aggregation: block-per-node, bucket scan ---------------
__global__ void k_agg(const float* __restrict__ protEmb) {
    int v = blockIdx.x;
    int t = threadIdx.x;                  // 128 threads = 128 cols
    int deg = g_deg[v];
    const int* bkt = g_bkt + v * BCAP;
    float sum = 0.f;
    int j = 0;
    for (; j + 8 <= deg; j += 8) {
        const float* p[8];
#pragma unroll
        for (int q = 0; q < 8; q++) {
            int s = bkt[j + q];           // broadcast load across warp
            p[q] = (s < ND) ? g_xd + s * EMB : protEmb + (s - ND) * EMB;
        }
        float v0 = p[0][t], v1 = p[1][t], v2 = p[2][t], v3 = p[3][t];
        float v4 = p[4][t], v5 = p[5][t], v6 = p[6][t], v7 = p[7][t];
        sum += ((v0 + v1) + (v2 + v3)) + ((v4 + v5) + (v6 + v7));
    }
    for (; j < deg; j++) {
        int s = bkt[j];
        const float* p = (s < ND) ? g_xd + s * EMB : protEmb + (s - ND) * EMB;
        sum += p[t];
    }
    float inv = 1.f / fmaxf((float)deg, 1.f);
    g_agg[v * EMB + t] = sum * inv;
}

// ---------------- fused: SAGE layer-1 + U/V projection ---------------------------
__global__ void k_sageuv(const float* __restrict__ bl) {
    int warp = (blockIdx.x * blockDim.x + threadIdx.x) >> 5;
    int lane = threadIdx.x & 31;
    if (warp >= ND) return;
    const float* a1 = g_agg + warp * EMB;
    const float* a2 = g_xd + warp * EMB;
    float4 acc = *(const float4*)(bl + lane * 4);
#pragma unroll
    for (int k0 = 0; k0 < EMB; k0 += 32) {
        float av1 = a1[k0 + lane];
        float av2 = a2[k0 + lane];
#pragma unroll
        for (int j = 0; j < 32; j++) {
            float x1 = __shfl_sync(0xffffffffu, av1, j);
            float x2 = __shfl_sync(0xffffffffu, av2, j);
            float4 wl = *(const float4*)&g_Wlt[(k0 + j) * EMB + lane * 4];
            float4 wr = *(const float4*)&g_Wrt[(k0 + j) * EMB + lane * 4];
            acc.x += x1 * wl.x + x2 * wr.x;
            acc.y += x1 * wl.y + x2 * wr.y;
            acc.z += x1 * wl.z + x2 * wr.z;
            acc.w += x1 * wl.w + x2 * wr.w;
        }
    }
    // x600 row (4 vals/lane, strided layout: value q lives at col q*32+lane)
    float xr[4];
    xr[0] = fmaxf(acc.x, 0.f); xr[1] = fmaxf(acc.y, 0.f);
    xr[2] = fmaxf(acc.z, 0.f); xr[3] = fmaxf(acc.w, 0.f);
    // NOTE: acc components are cols lane*4..lane*4+3 (contiguous), not strided.
    // Redo with correct mapping: value at col c = lane*4+q is xr[q].
    float4 u = make_float4(0.f, 0.f, 0.f, 0.f);
    float4 v = make_float4(0.f, 0.f, 0.f, 0.f);
#pragma unroll
    for (int j = 0; j < 32; j++) {
        // lane j holds cols 4j..4j+3 of x600
        float x0 = __shfl_sync(0xffffffffu, xr[0], j);
        float x1 = __shfl_sync(0xffffffffu, xr[1], j);
        float x2 = __shfl_sync(0xffffffffu, xr[2], j);
        float x3 = __shfl_sync(0xffffffffu, xr[3], j);
#pragma unroll
        for (int q = 0; q < 4; q++) {
            float x = (q == 0) ? x0 : (q == 1) ? x1 : (q == 2) ? x2 : x3;
            int k = 4 * j + q;
            float4 wu = *(const float4*)&g_W1pt[k * EMB + lane * 4];
            float4 wv = *(const float4*)&g_W1pt[(128 + k) * EMB + lane * 4];
            u.x += x * wu.x; u.y += x * wu.y; u.z += x * wu.z; u.w += x * wu.w;
            v.x += x * wv.x; v.y += x * wv.y; v.z += x * wv.z; v.w += x * wv.w;
        }
    }
    *(float4*)(g_U + warp * EMB + lane * 4) = u;
    *(float4*)(g_V + warp * EMB + lane * 4) = v;
}

// ---------------- fused: pair MLP + per-anchor dot -------------------------------
__global__ void k_final(const int* __restrict__ anch, const int* __restrict__ tpl,
                        const float* __restrict__ ob1, const float* __restrict__ oW2,
                        const float* __restrict__ ob2, float* __restrict__ out) {
    int w = (blockIdx.x * blockDim.x + threadIdx.x) >> 5;
    int lane = threadIdx.x & 31;
    if (w >= NANCH) return;
    int a = anch[w];
    int p = a / NSE;
    int s = a - p * NSE;
    int ia = tpl[2 * p], ib = tpl[2 * p + 1];
    float4 u = ((const float4*)g_U)[ia * 32 + lane];
    float4 v = ((const float4*)g_V)[ib * 32 + lane];
    float4 b = ((const float4*)ob1)[lane];
    float4 x;
    x.x = fmaxf(u.x + v.x + b.x, 0.f);
    x.y = fmaxf(u.y + v.y + b.y, 0.f);
    x.z = fmaxf(u.z + v.z + b.z, 0.f);
    x.w = fmaxf(u.w + v.w + b.w, 0.f);
    float4 y = ((const float4*)(oW2 + s * EMB))[lane];
    float d = x.x * y.x + x.y * y.y + x.z * y.z + x.w * y.w;
#pragma unroll
    for (int off = 16; off; off >>= 1) d += __shfl_xor_sync(0xffffffffu, d, off);
    if (lane == 0) out[w] = fmaxf(d + ob2[s], 0.f);
}

// ---------------- launch ----------------
extern "C" void kernel_launch(void* const* d_in, const int* in_sizes, int n_in,
                              void* d_out, int out_size) {
    const int*   ei      = (const int*)d_in[0];
    const float* drugF   = (const float*)d_in[1];
    const int*   tpl     = (const int*)d_in[2];
    const int*   anch    = (const int*)d_in[3];
    const float* W1      = (const float*)d_in[4];
    const float* b1      = (const float*)d_in[5];
    const float* W2      = (const float*)d_in[6];
    const float* b2      = (const float*)d_in[7];
    const float* protEmb = (const float*)d_in[8];
    const float* sageWl  = (const float*)d_in[9];
    const float* sagebl  = (const float*)d_in[10];
    const float* sageWr  = (const float*)d_in[11];
    const float* outW1   = (const float*)d_in[12];
    const float* outb1   = (const float*)d_in[13];
    const float* outW2   = (const float*)d_in[14];
    const float* outb2   = (const float*)d_in[15];
    float* out = (float*)d_out;

    k_init<<<81, 1024>>>(W2, sageWl + EMB * EMB, sageWr + EMB * EMB, outW1);
    k_mlp1<<<dim3(10, 32), dim3(32, 8)>>>(drugF, W1);
    k_edges<<<1184, 256>>>(ei);
    k_mlp12<<<75, 256>>>(b1, b2);
    k_agg<<<600, 128>>>(protEmb);
    k_sageuv<<<75, 256>>>(sagebl + EMB);
    k_final<<<1024, 256>>>(anch, tpl, outb1, outW2, outb2, out);
}

// round 4
// speedup vs baseline: 1.7804x; 1.6232x over previous
#include <cuda_runtime.h>

#define ND 600
#define NPRO 19081
#define NSE 964
#define EMB 128
#define FEAT 2048
#define NE 1200000
#define NPAIRS 8192
#define NANCH 8192
#define NV 19681
#define KSPLIT 32
#define MPAD 640
#define BCAP 160

// ---------------- scratch (static device globals; no allocation) ----------------
__device__ float g_part[KSPLIT * MPAD * EMB];   // mlp1 split-K partials (10.5 MB)
__device__ float g_xd[ND * EMB];                // relu MLP output == xF[:600]
__device__ float g_U[ND * EMB];                 // x600 @ Wa^T
__device__ float g_V[ND * EMB];                 // x600 @ Wb^T
__device__ int   g_deg[ND];                     // degree == bucket cursor
__device__ int   g_bkt[ND * BCAP];              // per-node src buckets
__device__ float g_W2t[EMB * EMB];              // W2^T        [k][o]
__device__ float g_Wlt[EMB * EMB];              // sageWl[1]^T [k][o]
__device__ float g_Wrt[EMB * EMB];              // sageWr[1]^T [k][o]
__device__ float g_W1pt[2 * EMB * EMB];         // outW1^T     [k(0..255)][o]

// ---------------- init: zero deg + transpose small weights ----------------
__global__ void k_init(const float* __restrict__ W2, const float* __restrict__ Wl,
                       const float* __restrict__ Wr, const float* __restrict__ oW1) {
    int idx = blockIdx.x * 1024 + threadIdx.x;          // 81 blocks: 82944 threads
    if (idx < 16384) {
        int k = idx >> 7, o = idx & 127;
        g_W2t[idx] = W2[o * 128 + k];
    } else if (idx < 32768) {
        int f = idx - 16384; int k = f >> 7, o = f & 127;
        g_Wlt[f] = Wl[o * 128 + k];
    } else if (idx < 49152) {
        int f = idx - 32768; int k = f >> 7, o = f & 127;
        g_Wrt[f] = Wr[o * 128 + k];
    } else if (idx < 81920) {
        int f = idx - 49152; int k = f >> 7, o = f & 127;   // k in [0,256)
        g_W1pt[f] = oW1[o * 256 + k];
    } else if (idx - 81920 < ND) {
        g_deg[idx - 81920] = 0;
    }
}

// ---------------- single edge pass: deg-count + bucket scatter --------------------
__global__ void k_edges(const int* __restrict__ ei) {
    int stride = gridDim.x * blockDim.x;
    for (int i = blockIdx.x * blockDim.x + threadIdx.x; i < NE; i += stride) {
        int d = ei[NE + i];
        if (d < ND) {
            int p = atomicAdd(&g_deg[d], 1);
            g_bkt[d * BCAP + p] = ei[i];
        }
    }
}

// ---------------- MLP1: split-K tiled SGEMM, M=600 K=2048 N=128 ----------------
// grid (19, 32): 32-row tile x full-N, 64-wide K slice. 256 threads (32x8), 4x4 micro.
__global__ void k_mlp1(const float* __restrict__ A, const float* __restrict__ W) {
    __shared__ __align__(16) float As[16][32];
    __shared__ __align__(16) float Bs[16][128];
    int tx = threadIdx.x, ty = threadIdx.y;
    int tid = ty * 32 + tx;
    int rowBase = blockIdx.x * 32;
    int kbase = blockIdx.y * 64;
    float acc[4][4];
#pragma unroll
    for (int i = 0; i < 4; i++)
#pragma unroll
        for (int j = 0; j < 4; j++) acc[i][j] = 0.f;

    for (int kk = 0; kk < 4; kk++) {
        // A chunk: 32 rows x 16 k = 128 float4s (threads 0..127)
        if (tid < 128) {
            int r = tid >> 2, c4 = tid & 3;
            int row = rowBase + r;
            float4 va = make_float4(0.f, 0.f, 0.f, 0.f);
            if (row < ND) va = *(const float4*)(A + row * FEAT + kbase + kk * 16 + c4 * 4);
            As[c4 * 4 + 0][r] = va.x; As[c4 * 4 + 1][r] = va.y;
            As[c4 * 4 + 2][r] = va.z; As[c4 * 4 + 3][r] = va.w;
        }
        // B chunk: 128 rows x 16 k = 512 float4s (2 per thread)
#pragma unroll
        for (int q = 0; q < 2; q++) {
            int idx = tid + q * 256;
            int wr = idx >> 2, wc = idx & 3;
            float4 vb = *(const float4*)(W + wr * FEAT + kbase + kk * 16 + wc * 4);
            Bs[wc * 4 + 0][wr] = vb.x; Bs[wc * 4 + 1][wr] = vb.y;
            Bs[wc * 4 + 2][wr] = vb.z; Bs[wc * 4 + 3][wr] = vb.w;
        }
        __syncthreads();
#pragma unroll
        for (int k = 0; k < 16; k++) {
            float a[4], b[4];
            *(float4*)(a) = *(const float4*)&As[k][ty * 4];
            *(float4*)(b) = *(const float4*)&Bs[k][tx * 4];
#pragma unroll
            for (int i = 0; i < 4; i++)
#pragma unroll
                for (int j = 0; j < 4; j++) acc[i][j] += a[i] * b[j];
        }
        __syncthreads();
    }
    float* out = g_part + blockIdx.y * (MPAD * EMB) + rowBase * EMB;
#pragma unroll
    for (int i = 0; i < 4; i++) {
        float4 v = make_float4(acc[i][0], acc[i][1], acc[i][2], acc[i][3]);
        *(float4*)(out + (ty * 4 + i) * EMB + tx * 4) = v;
    }
}

// ---------------- fused: split-K reduce + bias + relu + MLP2 ----------------------
// block-per-row: 600 blocks x 128 threads (one thread per column)
__global__ void k_mlp12(const float* __restrict__ b1, const float* __restrict__ b2) {
    int row = blockIdx.x, t = threadIdx.x;
    __shared__ float sh[128];
    float s = b1[t];
    const float* p = g_part + row * EMB + t;
#pragma unroll
    for (int ks = 0; ks < KSPLIT; ks++) s += p[ks * (MPAD * EMB)];
    sh[t] = fmaxf(s, 0.f);
    __syncthreads();
    float a0 = b2[t], a1 = 0.f, a2 = 0.f, a3 = 0.f;
#pragma unroll
    for (int k = 0; k < 128; k += 4) {
        a0 += sh[k + 0] * g_W2t[(k + 0) * 128 + t];
        a1 += sh[k + 1] * g_W2t[(k + 1) * 128 + t];
        a2 += sh[k + 2] * g_W2t[(k + 2) * 128 + t];
        a3 += sh[k + 3] * g_W2t[(k + 3) * 128 + t];
    }
    g_xd[row * EMB + t] = fmaxf((a0 + a1) + (a2 + a3), 0.f);
}

// ---------------- fused: aggregation + SAGE layer-1 + U/V projection -------------
// block-per-node: 600 blocks x 128 threads
__global__ void k_aggsage(const float* __restrict__ protEmb, const float* __restrict__ bl) {
    int v = blockIdx.x;
    int t = threadIdx.x;
    __shared__ float s1[128], s2[128], sx[128];
    int deg = g_deg[v];
    const int* bkt = g_bkt + v * BCAP;
    float sum = 0.f;
    int j = 0;
    for (; j + 8 <= deg; j += 8) {
        const float* p[8];
#pragma unroll
        for (int q = 0; q < 8; q++) {
            int s = bkt[j + q];           // broadcast load across warp
            p[q] = (s < ND) ? g_xd + s * EMB : protEmb + (s - ND) * EMB;
        }
        float v0 = p[0][t], v1 = p[1][t], v2 = p[2][t], v3 = p[3][t];
        float v4 = p[4][t], v5 = p[5][t], v6 = p[6][t], v7 = p[7][t];
        sum += ((v0 + v1) + (v2 + v3)) + ((v4 + v5) + (v6 + v7));
    }
    for (; j < deg; j++) {
        int s = bkt[j];
        const float* p = (s < ND) ? g_xd + s * EMB : protEmb + (s - ND) * EMB;
        sum += p[t];
    }
    s1[t] = sum * (1.f / fmaxf((float)deg, 1.f));
    s2[t] = g_xd[v * EMB + t];
    __syncthreads();
    // sage: col t = relu( sum_k s1[k]*Wl[t][k] + s2[k]*Wr[t][k] + bl[t] )
    float a0 = bl[t], a1 = 0.f;
#pragma unroll
    for (int k = 0; k < 128; k += 2) {
        a0 += s1[k] * g_Wlt[k * 128 + t] + s2[k] * g_Wrt[k * 128 + t];
        a1 += s1[k + 1] * g_Wlt[(k + 1) * 128 + t] + s2[k + 1] * g_Wrt[(k + 1) * 128 + t];
    }
    sx[t] = fmaxf(a0 + a1, 0.f);
    __syncthreads();
    // U/V projection
    float u0 = 0.f, u1 = 0.f, v0 = 0.f, v1 = 0.f;
#pragma unroll
    for (int k = 0; k < 128; k += 2) {
        u0 += sx[k] * g_W1pt[k * 128 + t];
        v0 += sx[k] * g_W1pt[(128 + k) * 128 + t];
        u1 += sx[k + 1] * g_W1pt[(k + 1) * 128 + t];
        v1 += sx[k + 1] * g_W1pt[(129 + k) * 128 + t];
    }
    g_U[v * EMB + t] = u0 + u1;
    g_V[v * EMB + t] = v0 + v1;
}

// ---------------- fused: pair MLP + per-anchor dot -------------------------------
__global__ void k_final(const int* __restrict__ anch, const int* __restrict__ tpl,
                        const float* __restrict__ ob1, const float* __restrict__ oW2,
                        const float* __restrict__ ob2, float* __restrict__ out) {
    int w = (blockIdx.x * blockDim.x + threadIdx.x) >> 5;
    int lane = threadIdx.x & 31;
    if (w >= NANCH) return;
    int a = anch[w];
    int p = a / NSE;
    int s = a - p * NSE;
    int ia = tpl[2 * p], ib = tpl[2 * p + 1];
    float4 u = ((const float4*)g_U)[ia * 32 + lane];
    float4 v = ((const float4*)g_V)[ib * 32 + lane];
    float4 b = ((const float4*)ob1)[lane];
    float4 x;
    x.x = fmaxf(u.x + v.x + b.x, 0.f);
    x.y = fmaxf(u.y + v.y + b.y, 0.f);
    x.z = fmaxf(u.z + v.z + b.z, 0.f);
    x.w = fmaxf(u.w + v.w + b.w, 0.f);
    float4 y = ((const float4*)(oW2 + s * EMB))[lane];
    float d = x.x * y.x + x.y * y.y + x.z * y.z + x.w * y.w;
#pragma unroll
    for (int off = 16; off; off >>= 1) d += __shfl_xor_sync(0xffffffffu, d, off);
    if (lane == 0) out[w] = fmaxf(d + ob2[s], 0.f);
}

// ---------------- launch ----------------
extern "C" void kernel_launch(void* const* d_in, const int* in_sizes, int n_in,
                              void* d_out, int out_size) {
    const int*   ei      = (const int*)d_in[0];
    const float* drugF   = (const float*)d_in[1];
    const int*   tpl     = (const int*)d_in[2];
    const int*   anch    = (const int*)d_in[3];
    const float* W1      = (const float*)d_in[4];
    const float* b1      = (const float*)d_in[5];
    const float* W2      = (const float*)d_in[6];
    const float* b2      = (const float*)d_in[7];
    const float* protEmb = (const float*)d_in[8];
    const float* sageWl  = (const float*)d_in[9];
    const float* sagebl  = (const float*)d_in[10];
    const float* sageWr  = (const float*)d_in[11];
    const float* outW1   = (const float*)d_in[12];
    const float* outb1   = (const float*)d_in[13];
    const float* outW2   = (const float*)d_in[14];
    const float* outb2   = (const float*)d_in[15];
    float* out = (float*)d_out;

    k_init<<<81, 1024>>>(W2, sageWl + EMB * EMB, sageWr + EMB * EMB, outW1);
    k_mlp1<<<dim3(19, 32), dim3(32, 8)>>>(drugF, W1);
    k_edges<<<1184, 256>>>(ei);
    k_mlp12<<<600, 128>>>(b1, b2);
    k_aggsage<<<600, 128>>>(protEmb, sagebl + EMB);
    k_final<<<1024, 256>>>(anch, tpl, outb1, outW2, outb2, out);
}

// round 5
// speedup vs baseline: 1.9343x; 1.0864x over previous
#include <cuda_runtime.h>

#define ND 600
#define NPRO 19081
#define NSE 964
#define EMB 128
#define FEAT 2048
#define NE 1200000
#define NPAIRS 8192
#define NANCH 8192
#define NV 19681
#define KSPLIT 32
#define MPAD 640
#define BCAP 160

// phase-1 block-role partition (all 256-thread blocks)
#define EDGE_BLKS 516
#define MLP1_BLKS 608          /* 19 row-tiles x 32 k-splits */
#define INIT_BLKS 320          /* 81920 transpose elements / 256 */
#define P1_GRID (EDGE_BLKS + MLP1_BLKS + INIT_BLKS)

// ---------------- scratch (static device globals; zero-initialized at load) -----
__device__ float g_part[KSPLIT * MPAD * EMB];   // mlp1 split-K partials
__device__ float g_xd[ND * EMB];                // relu MLP output == xF[:600]
__device__ float g_U[ND * EMB];                 // x600 @ Wa^T
__device__ float g_V[ND * EMB];                 // x600 @ Wb^T
__device__ int   g_deg[ND];                     // degree == bucket cursor (zeroed by k_final tail)
__device__ int   g_bkt[ND * BCAP];              // per-node src buckets
__device__ float g_W2t[EMB * EMB];              // W2^T        [k][o]
__device__ float g_Wlt[EMB * EMB];              // sageWl[1]^T [k][o]
__device__ float g_Wrt[EMB * EMB];              // sageWr[1]^T [k][o]
__device__ float g_W1pt[2 * EMB * EMB];         // outW1^T     [k(0..255)][o]

// ================= phase 1: edges scatter + MLP1 split-K GEMM + weight transposes
__global__ void k_phase1(const int* __restrict__ ei,
                         const float* __restrict__ A, const float* __restrict__ W,
                         const float* __restrict__ W2, const float* __restrict__ Wl,
                         const float* __restrict__ Wr, const float* __restrict__ oW1) {
    __shared__ __align__(16) float As[16][32];
    __shared__ __align__(16) float Bs[16][128];
    int b = blockIdx.x;
    int t = threadIdx.x;

    if (b < EDGE_BLKS) {
        // ---- edge role: int4 over dst, bucket-scatter src for dst<ND ----
        const int4* dst4 = (const int4*)(ei + NE);
        int stride = EDGE_BLKS * 256;
        for (int i = b * 256 + t; i < NE / 4; i += stride) {
            int4 d4 = dst4[i];
            int base = i * 4;
            if (d4.x < ND) { int p = atomicAdd(&g_deg[d4.x], 1); g_bkt[d4.x * BCAP + p] = ei[base + 0]; }
            if (d4.y < ND) { int p = atomicAdd(&g_deg[d4.y], 1); g_bkt[d4.y * BCAP + p] = ei[base + 1]; }
            if (d4.z < ND) { int p = atomicAdd(&g_deg[d4.z], 1); g_bkt[d4.z * BCAP + p] = ei[base + 2]; }
            if (d4.w < ND) { int p = atomicAdd(&g_deg[d4.w], 1); g_bkt[d4.w * BCAP + p] = ei[base + 3]; }
        }
        return;
    }
    if (b < EDGE_BLKS + MLP1_BLKS) {
        // ---- MLP1 role: 32-row tile x 64-wide K slice, 4x4 micro-tile ----
        int b2 = b - EDGE_BLKS;
        int rt = b2 % 19, ks = b2 / 19;
        int tx = t & 31, ty = t >> 5;
        int rowBase = rt * 32;
        int kbase = ks * 64;
        float acc[4][4];
#pragma unroll
        for (int i = 0; i < 4; i++)
#pragma unroll
            for (int j = 0; j < 4; j++) acc[i][j] = 0.f;

        for (int kk = 0; kk < 4; kk++) {
            if (t < 128) {
                int r = t >> 2, c4 = t & 3;
                int row = rowBase + r;
                float4 va = make_float4(0.f, 0.f, 0.f, 0.f);
                if (row < ND) va = *(const float4*)(A + row * FEAT + kbase + kk * 16 + c4 * 4);
                As[c4 * 4 + 0][r] = va.x; As[c4 * 4 + 1][r] = va.y;
                As[c4 * 4 + 2][r] = va.z; As[c4 * 4 + 3][r] = va.w;
            }
#pragma unroll
            for (int q = 0; q < 2; q++) {
                int idx = t + q * 256;
                int wr = idx >> 2, wc = idx & 3;
                float4 vb = *(const float4*)(W + wr * FEAT + kbase + kk * 16 + wc * 4);
                Bs[wc * 4 + 0][wr] = vb.x; Bs[wc * 4 + 1][wr] = vb.y;
                Bs[wc * 4 + 2][wr] = vb.z; Bs[wc * 4 + 3][wr] = vb.w;
            }
            __syncthreads();
#pragma unroll
            for (int k = 0; k < 16; k++) {
                float a[4], bb[4];
                *(float4*)(a)  = *(const float4*)&As[k][ty * 4];
                *(float4*)(bb) = *(const float4*)&Bs[k][tx * 4];
#pragma unroll
                for (int i = 0; i < 4; i++)
#pragma unroll
                    for (int j = 0; j < 4; j++) acc[i][j] += a[i] * bb[j];
            }
            __syncthreads();
        }
        float* out = g_part + ks * (MPAD * EMB) + rowBase * EMB;
#pragma unroll
        for (int i = 0; i < 4; i++) {
            float4 v = make_float4(acc[i][0], acc[i][1], acc[i][2], acc[i][3]);
            *(float4*)(out + (ty * 4 + i) * EMB + tx * 4) = v;
        }
        return;
    }
    // ---- init role: transpose small weights ----
    int idx = (b - EDGE_BLKS - MLP1_BLKS) * 256 + t;       // [0, 81920)
    if (idx < 16384) {
        int k = idx >> 7, o = idx & 127;
        g_W2t[idx] = W2[o * 128 + k];
    } else if (idx < 32768) {
        int f = idx - 16384; int k = f >> 7, o = f & 127;
        g_Wlt[f] = Wl[o * 128 + k];
    } else if (idx < 49152) {
        int f = idx - 32768; int k = f >> 7, o = f & 127;
        g_Wrt[f] = Wr[o * 128 + k];
    } else {
        int f = idx - 49152; int k = f >> 7, o = f & 127;   // k in [0,256)
        g_W1pt[f] = oW1[o * 256 + k];
    }
}

// ================= phase 2: split-K reduce + bias + relu + MLP2 (600 x 512) ======
__global__ void k_mlp12(const float* __restrict__ b1, const float* __restrict__ b2) {
    int row = blockIdx.x;
    int t = threadIdx.x;            // 512
    int col = t & 127, q = t >> 7;  // q in [0,4)
    __shared__ float red[512];
    __shared__ float hs[128];
    float s = 0.f;
    const float* p = g_part + row * EMB + col;
#pragma unroll
    for (int i = 0; i < 8; i++) s += p[(q * 8 + i) * (MPAD * EMB)];
    red[t] = s;
    __syncthreads();
    if (t < 128) {
        float h = red[t] + red[t + 128] + red[t + 256] + red[t + 384] + b1[t];
        hs[t] = fmaxf(h, 0.f);
    }
    __syncthreads();
    // MLP2: out[col] = relu(sum_k hs[k] * W2t[k][col] + b2[col]); K split 4 ways
    float a0 = 0.f, a1 = 0.f;
#pragma unroll
    for (int k = 0; k < 32; k += 2) {
        int kk = q * 32 + k;
        a0 += hs[kk] * g_W2t[kk * 128 + col];
        a1 += hs[kk + 1] * g_W2t[(kk + 1) * 128 + col];
    }
    red[t] = a0 + a1;
    __syncthreads();
    if (t < 128) {
        float r = red[t] + red[t + 128] + red[t + 256] + red[t + 384] + b2[t];
        g_xd[row * EMB + t] = fmaxf(r, 0.f);
    }
}

// ================= phase 3: aggregation + SAGE layer-1 + U/V (600 x 128) =========
__global__ void k_aggsage(const float* __restrict__ protEmb, const float* __restrict__ bl) {
    int v = blockIdx.x;
    int t = threadIdx.x;
    __shared__ float s1[128], s2[128], sx[128];
    int deg = g_deg[v];
    const int* bkt = g_bkt + v * BCAP;
    float sum = 0.f;
    int j = 0;
    for (; j + 8 <= deg; j += 8) {
        const float* p[8];
#pragma unroll
        for (int q = 0; q < 8; q++) {
            int s = bkt[j + q];
            p[q] = (s < ND) ? g_xd + s * EMB : protEmb + (s - ND) * EMB;
        }
        float v0 = p[0][t], v1 = p[1][t], v2 = p[2][t], v3 = p[3][t];
        float v4 = p[4][t], v5 = p[5][t], v6 = p[6][t], v7 = p[7][t];
        sum += ((v0 + v1) + (v2 + v3)) + ((v4 + v5) + (v6 + v7));
    }
    for (; j < deg; j++) {
        int s = bkt[j];
        const float* p = (s < ND) ? g_xd + s * EMB : protEmb + (s - ND) * EMB;
        sum += p[t];
    }
    s1[t] = sum * (1.f / fmaxf((float)deg, 1.f));
    s2[t] = g_xd[v * EMB + t];
    __syncthreads();
    float a0 = bl[t], a1 = 0.f;
#pragma unroll
    for (int k = 0; k < 128; k += 2) {
        a0 += s1[k] * g_Wlt[k * 128 + t] + s2[k] * g_Wrt[k * 128 + t];
        a1 += s1[k + 1] * g_Wlt[(k + 1) * 128 + t] + s2[k + 1] * g_Wrt[(k + 1) * 128 + t];
    }
    sx[t] = fmaxf(a0 + a1, 0.f);
    __syncthreads();
    float u0 = 0.f, u1 = 0.f, v0 = 0.f, v1 = 0.f;
#pragma unroll
    for (int k = 0; k < 128; k += 2) {
        u0 += sx[k] * g_W1pt[k * 128 + t];
        v0 += sx[k] * g_W1pt[(128 + k) * 128 + t];
        u1 += sx[k + 1] * g_W1pt[(k + 1) * 128 + t];
        v1 += sx[k + 1] * g_W1pt[(129 + k) * 128 + t];
    }
    g_U[v * EMB + t] = u0 + u1;
    g_V[v * EMB + t] = v0 + v1;
}

// ================= phase 4: pair MLP + per-anchor dot (+ deg re-zero tail) =======
__global__ void k_final(const int* __restrict__ anch, const int* __restrict__ tpl,
                        const float* __restrict__ ob1, const float* __restrict__ oW2,
                        const float* __restrict__ ob2, float* __restrict__ out) {
    int gid = blockIdx.x * blockDim.x + threadIdx.x;
    if (gid < ND) g_deg[gid] = 0;     // reset cursor for the NEXT call/replay
    int w = gid >> 5;
    int lane = threadIdx.x & 31;
    if (w >= NANCH) return;
    int a = anch[w];
    int p = a / NSE;
    int s = a - p * NSE;
    int ia = tpl[2 * p], ib = tpl[2 * p + 1];
    float4 u = ((const float4*)g_U)[ia * 32 + lane];
    float4 v = ((const float4*)g_V)[ib * 32 + lane];
    float4 b = ((const float4*)ob1)[lane];
    float4 x;
    x.x = fmaxf(u.x + v.x + b.x, 0.f);
    x.y = fmaxf(u.y + v.y + b.y, 0.f);
    x.z = fmaxf(u.z + v.z + b.z, 0.f);
    x.w = fmaxf(u.w + v.w + b.w, 0.f);
    float4 y = ((const float4*)(oW2 + s * EMB))[lane];
    float d = x.x * y.x + x.y * y.y + x.z * y.z + x.w * y.w;
#pragma unroll
    for (int off = 16; off; off >>= 1) d += __shfl_xor_sync(0xffffffffu, d, off);
    if (lane == 0) out[w] = fmaxf(d + ob2[s], 0.f);
}

// ---------------- launch ----------------
extern "C" void kernel_launch(void* const* d_in, const int* in_sizes, int n_in,
                              void* d_out, int out_size) {
    const int*   ei      = (const int*)d_in[0];
    const float* drugF   = (const float*)d_in[1];
    const int*   tpl     = (const int*)d_in[2];
    const int*   anch    = (const int*)d_in[3];
    const float* W1      = (const float*)d_in[4];
    const float* b1      = (const float*)d_in[5];
    const float* W2      = (const float*)d_in[6];
    const float* b2      = (const float*)d_in[7];
    const float* protEmb = (const float*)d_in[8];
    const float* sageWl  = (const float*)d_in[9];
    const float* sagebl  = (const float*)d_in[10];
    const float* sageWr  = (const float*)d_in[11];
    const float* outW1   = (const float*)d_in[12];
    const float* outb1   = (const float*)d_in[13];
    const float* outW2   = (const float*)d_in[14];
    const float* outb2   = (const float*)d_in[15];
    float* out = (float*)d_out;

    k_phase1<<<P1_GRID, 256>>>(ei, drugF, W1,
                               W2, sageWl + EMB * EMB, sageWr + EMB * EMB, outW1);
    k_mlp12<<<600, 512>>>(b1, b2);
    k_aggsage<<<600, 128>>>(protEmb, sagebl + EMB);
    k_final<<<1024, 256>>>(anch, tpl, outb1, outW2, outb2, out);
}